// round 7
// baseline (speedup 1.0000x reference)
#include <cuda_runtime.h>
#include <cuda_bf16.h>
#include <math.h>

// Problem constants
#define B_  16
#define C_  4
#define J_  19
#define T_  256
#define S_  10
#define NCH (C_*J_*T_)              // 19456 BN channels
#define NPIX (B_*T_*S_)             // 40960 pixels
#define NCOLS (NPIX*J_)             // 778240 (pixel, joint) columns
#define EPSV 1e-5f

typedef unsigned long long u64;

// ---- f32x2 packed-math helpers ------------------------------------------------
__device__ __forceinline__ u64 dup2(float a) {
    u64 r; asm("mov.b64 %0, {%1, %1};" : "=l"(r) : "f"(a)); return r;
}
__device__ __forceinline__ void upk2(u64 v, float& lo, float& hi) {
    asm("mov.b64 {%0, %1}, %2;" : "=f"(lo), "=f"(hi) : "l"(v));
}
__device__ __forceinline__ void fma2(u64& d, u64 a, u64 b) {
    asm("fma.rn.f32x2 %0, %1, %2, %0;" : "+l"(d) : "l"(a), "l"(b));
}
__device__ __forceinline__ void lds_v2u64(const float* p, u64& lo, u64& hi) {
    unsigned a = (unsigned)__cvta_generic_to_shared(p);
    asm("ld.shared.v2.u64 {%0, %1}, [%2];" : "=l"(lo), "=l"(hi) : "r"(a));
}

// ---------------- device scratch ----------------------------------------------
__device__ float g_bn_a[NCH];
__device__ float g_bn_b[NCH];
__device__ float g_w1t[C_*64];
__device__ float g_w2t[64*64];
__device__ float g_Mt[64*64];
__device__ float g_v[64];
__device__ float g_xnT[(size_t)4 * NCOLS];   // [c][pix*19+j]
__device__ float g_HT [(size_t)64 * NCOLS];  // [c][pix*19+j]
__device__ float g_AG [(size_t)64 * NCOLS];  // [c][b*48640 + j*2560 + ts]

// ---------------- kernel 1: BN statistics ---------------------------------------
__global__ void bn_stats_kernel(const float* __restrict__ x,
                                const float* __restrict__ gamma,
                                const float* __restrict__ beta) {
    int ch = blockIdx.x * 8 + (threadIdx.x >> 5);
    if (ch >= NCH) return;
    int lane = threadIdx.x & 31;
    float s = 0.f, ss = 0.f;
    for (int e = lane; e < B_ * S_; e += 32) {
        int b = e / S_, si = e % S_;
        float v = x[(b * NCH + ch) * S_ + si];
        s += v; ss += v * v;
    }
    #pragma unroll
    for (int off = 16; off; off >>= 1) {
        s  += __shfl_xor_sync(0xffffffffu, s,  off);
        ss += __shfl_xor_sync(0xffffffffu, ss, off);
    }
    if (lane == 0) {
        const float inv_n = 1.f / (float)(B_ * S_);
        float mean = s * inv_n;
        float var  = ss * inv_n - mean * mean;
        float a = gamma[ch] * rsqrtf(var + EPSV);
        g_bn_a[ch] = a;
        g_bn_b[ch] = beta[ch] - mean * a;
    }
}

// ---------------- kernel 2: precompute M, v, transposed weights -----------------
__global__ void setup_kernel(const float* __restrict__ w1,
                             const float* __restrict__ w2,
                             const float* __restrict__ ws1,
                             const float* __restrict__ bs1,
                             const float* __restrict__ ws2) {
    int idx = blockIdx.x * blockDim.x + threadIdx.x;
    if (idx < 4096) {
        int b = idx >> 6, a = idx & 63;
        float acc = 0.f;
        #pragma unroll 4
        for (int s = 0; s < 128; ++s)
            acc += ws1[s * 64 + a] * ws2[s * 64 + b];
        g_Mt[b * 64 + a] = acc;
        g_w2t[idx] = w2[(idx & 63) * 64 + (idx >> 6)];
    }
    if (idx < C_ * 64) g_w1t[idx] = w1[(idx & 63) * C_ + (idx >> 6)];
    if (idx < 64) {
        float acc = 0.f;
        #pragma unroll 4
        for (int s = 0; s < 128; ++s)
            acc += ws2[s * 64 + idx] * bs1[s];
        g_v[idx] = acc;
    }
}

// ---------------- kernel 3: BN-apply + transpose to column-major ----------------
#define XTK 8
__global__ void xn_kernel(const float* __restrict__ x) {
    __shared__ float sa[76 * XTK];
    __shared__ float sb[76 * XTK];
    __shared__ float tile[80 * 80];
    int b  = blockIdx.x >> 5;
    int t0 = (blockIdx.x & 31) * XTK;
    int tid = threadIdx.x;

    for (int u = tid; u < 76 * XTK; u += 256) {
        int ch = u / XTK, tt = u % XTK;
        sa[u] = g_bn_a[ch * 256 + t0 + tt];
        sb[u] = g_bn_b[ch * 256 + t0 + tt];
    }
    __syncthreads();

    for (int u = tid; u < 76 * 20; u += 256) {
        int ch = u / 20, i4 = (u % 20) * 4;
        float4 v = *(const float4*)&x[((size_t)(b * 76 + ch)) * 2560 + t0 * 10 + i4];
        #pragma unroll
        for (int q = 0; q < 4; ++q) {
            int i = i4 + q;
            int tt = i / 10;
            tile[i * 80 + ch] = (&v.x)[q] * sa[ch * XTK + tt] + sb[ch * XTK + tt];
        }
    }
    __syncthreads();

    for (int u = tid; u < 80 * 76; u += 256) {
        int i = u / 76, ch = u % 76;
        int c = ch / 19, j = ch % 19;
        g_xnT[(size_t)c * NCOLS + (size_t)(b * 2560 + t0 * 10 + i) * 19 + j] =
            tile[i * 80 + ch];
    }
}

// ---------------- g1: fused embed GEMMs (per-column, acts in regs) --------------
__global__ __launch_bounds__(320, 1)
void g1_kernel(const float* __restrict__ b1g, const float* __restrict__ b2g) {
    __shared__ float sw1[256];
    __shared__ float sb1[64];
    __shared__ float sb2[64];
    __shared__ float sw2[4096];
    int tid = threadIdx.x;
    for (int q = tid; q < 1024; q += 320)
        *(float4*)&sw2[q * 4] = *(const float4*)&g_w2t[q * 4];
    if (tid < 64) {
        *(float4*)&sw1[tid * 4] = *(const float4*)&g_w1t[tid * 4];
        sb1[tid] = b1g[tid];
        sb2[tid] = b2g[tid];
    }
    __syncthreads();

    size_t n = (size_t)blockIdx.x * 320 + tid;
    float x0 = g_xnT[n];
    float x1 = g_xnT[NCOLS + n];
    float x2 = g_xnT[2 * (size_t)NCOLS + n];
    float x3 = g_xnT[3 * (size_t)NCOLS + n];

    float h1[64];
    #pragma unroll
    for (int d = 0; d < 64; ++d)
        h1[d] = fmaxf(sb1[d] + sw1[d] * x0 + sw1[64 + d] * x1
                             + sw1[128 + d] * x2 + sw1[192 + d] * x3, 0.f);

    u64 acc[32];
    #pragma unroll
    for (int q = 0; q < 16; ++q) {
        u64 lo, hi; lds_v2u64(&sb2[q * 4], lo, hi);
        acc[2 * q] = lo; acc[2 * q + 1] = hi;
    }
    #pragma unroll
    for (int k = 0; k < 64; ++k) {
        u64 a2 = dup2(h1[k]);
        #pragma unroll
        for (int q = 0; q < 16; ++q) {
            u64 lo, hi; lds_v2u64(&sw2[k * 64 + q * 4], lo, hi);
            fma2(acc[2 * q], lo, a2);
            fma2(acc[2 * q + 1], hi, a2);
        }
    }
    #pragma unroll
    for (int i = 0; i < 32; ++i) {
        float lo, hi; upk2(acc[i], lo, hi);
        g_HT[(size_t)(2 * i) * NCOLS + n]     = fmaxf(lo, 0.f);
        g_HT[(size_t)(2 * i + 1) * NCOLS + n] = fmaxf(hi, 0.f);
    }
}

// ---------------- g2: per-8-pixel attention (G, logits, softmax, AGG) -----------
#define AST2 160
#define G2_M    0        // 4096
#define G2_V    4096     // 64
#define G2_LT   4160     // 8*19*20 = 3040  [p][j][k(20)]
#define G2_VH   7200     // 160  [p*20+k]
#define G2_H    7360     // 64*160 = 10240
#define G2_G    17600    // 64*160 = 10240 (later AGG [c][j*8+p])
#define G2_FLOATS 27840
#define G2_BYTES (G2_FLOATS * 4)   // 111,360 -> 2 blocks/SM

__global__ __launch_bounds__(256, 2)
void g2_kernel() {
    extern __shared__ float sm[];
    int tid = threadIdx.x;
    for (int q = tid; q < 1024; q += 256)
        *(float4*)&sm[G2_M + q * 4] = *(const float4*)&g_Mt[q * 4];
    if (tid < 64) sm[G2_V + tid] = g_v[tid];

    size_t n0 = (size_t)blockIdx.x * 152;
    for (int u = tid; u < 64 * 38; u += 256) {
        int c = u / 38, q = u % 38;
        float4 v = *(const float4*)&g_HT[(size_t)c * NCOLS + n0 + q * 4];
        #pragma unroll
        for (int e = 0; e < 4; ++e) {
            int i = q * 4 + e;
            int p = i / 19, j = i % 19;
            sm[G2_H + c * AST2 + p * 20 + j] = (&v.x)[e];
        }
    }
    __syncthreads();

    // ---- G = M H (8x8 tiles, tid<160); vh (tid>=160) ----
    if (tid < 160) {
        int dg = tid / 20, cg = tid % 20;
        int d0 = dg * 8, col0 = cg * 8;
        u64 acc[8][4];
        #pragma unroll
        for (int i = 0; i < 8; ++i)
            #pragma unroll
            for (int q = 0; q < 4; ++q) acc[i][q] = 0ull;
        #pragma unroll 4
        for (int k = 0; k < 64; ++k) {
            float4 w0 = *(const float4*)&sm[G2_M + k * 64 + d0];
            float4 w1 = *(const float4*)&sm[G2_M + k * 64 + d0 + 4];
            u64 a01, a23, a45, a67;
            lds_v2u64(&sm[G2_H + k * AST2 + col0], a01, a23);
            lds_v2u64(&sm[G2_H + k * AST2 + col0 + 4], a45, a67);
            #pragma unroll
            for (int i = 0; i < 8; ++i) {
                u64 wd = dup2(i < 4 ? (&w0.x)[i] : (&w1.x)[i - 4]);
                fma2(acc[i][0], wd, a01); fma2(acc[i][1], wd, a23);
                fma2(acc[i][2], wd, a45); fma2(acc[i][3], wd, a67);
            }
        }
        #pragma unroll
        for (int i = 0; i < 8; ++i) {
            float v0,v1,v2,v3,v4,v5,v6,v7;
            upk2(acc[i][0], v0, v1); upk2(acc[i][1], v2, v3);
            upk2(acc[i][2], v4, v5); upk2(acc[i][3], v6, v7);
            *(float4*)&sm[G2_G + (d0 + i) * AST2 + col0]     = make_float4(v0, v1, v2, v3);
            *(float4*)&sm[G2_G + (d0 + i) * AST2 + col0 + 4] = make_float4(v4, v5, v6, v7);
        }
    } else {
        for (int u = tid - 160; u < 160; u += 96) {
            float a = 0.f;
            #pragma unroll 8
            for (int b = 0; b < 64; ++b)
                a += sm[G2_V + b] * sm[G2_H + b * AST2 + u];
            sm[G2_VH + u] = a;
        }
    }
    __syncthreads();

    // ---- logits LT[p][j][k] = sum_a H[a][j] G[a][k] ----
    if (tid < 200) {
        int p  = tid / 25, r = tid % 25;
        int j0 = (r % 5) * 4, k0 = (r / 5) * 4;   // {0,4,8,12,16}
        u64 acc2[4][2];
        #pragma unroll
        for (int e = 0; e < 4; ++e) { acc2[e][0] = 0ull; acc2[e][1] = 0ull; }
        #pragma unroll 4
        for (int a = 0; a < 64; ++a) {
            float h0 = sm[G2_H + a * AST2 + p * 20 + j0];
            float h1 = sm[G2_H + a * AST2 + p * 20 + j0 + 1];
            float h2 = sm[G2_H + a * AST2 + p * 20 + j0 + 2];
            float h3 = sm[G2_H + a * AST2 + p * 20 + j0 + 3];
            u64 g01, g23;
            lds_v2u64(&sm[G2_G + a * AST2 + p * 20 + k0], g01, g23);
            u64 hd0 = dup2(h0), hd1 = dup2(h1), hd2 = dup2(h2), hd3 = dup2(h3);
            fma2(acc2[0][0], hd0, g01); fma2(acc2[0][1], hd0, g23);
            fma2(acc2[1][0], hd1, g01); fma2(acc2[1][1], hd1, g23);
            fma2(acc2[2][0], hd2, g01); fma2(acc2[2][1], hd2, g23);
            fma2(acc2[3][0], hd3, g01); fma2(acc2[3][1], hd3, g23);
        }
        #pragma unroll
        for (int e = 0; e < 4; ++e) {
            if (j0 + e < J_) {
                float l0, l1, l2, l3;
                upk2(acc2[e][0], l0, l1); upk2(acc2[e][1], l2, l3);
                *(float4*)&sm[G2_LT + p * 380 + (j0 + e) * 20 + k0] =
                    make_float4(l0, l1, l2, l3);
            }
        }
    }
    __syncthreads();

    // ---- softmax over k per (p, j) ----
    if (tid < 152) {
        int p = tid / J_, j = tid % J_;
        int lb = G2_LT + p * 380 + j * 20;
        float l[J_];
        float mx = -1e30f;
        #pragma unroll
        for (int k = 0; k < J_; ++k) {
            l[k] = sm[lb + k] + sm[G2_VH + p * 20 + k];
            mx = fmaxf(mx, l[k]);
        }
        float sum = 0.f;
        #pragma unroll
        for (int k = 0; k < J_; ++k) { l[k] = __expf(l[k] - mx); sum += l[k]; }
        float inv = 1.f / sum;
        #pragma unroll
        for (int k = 0; k < J_; ++k) sm[lb + k] = l[k] * inv;
    }
    __syncthreads();

    // ---- AGG[c][j*8+p] = sum_k H[c][p*20+k] att[p][j][k]  -> G buffer ----
    for (int v = tid; v < 320; v += 256) {
        int c0 = (v & 7) * 8;
        int rest = v >> 3;
        int p = rest & 7;
        int j0 = (rest >> 3) * 4;
        float acc[8][4];
        #pragma unroll
        for (int i = 0; i < 8; ++i)
            #pragma unroll
            for (int r = 0; r < 4; ++r) acc[i][r] = 0.f;
        #pragma unroll
        for (int k = 0; k < J_; ++k) {
            float at[4], h[8];
            #pragma unroll
            for (int r = 0; r < 4; ++r)
                at[r] = sm[G2_LT + p * 380 + (j0 + r) * 20 + k];
            #pragma unroll
            for (int i = 0; i < 8; ++i)
                h[i] = sm[G2_H + (c0 + i) * AST2 + p * 20 + k];
            #pragma unroll
            for (int i = 0; i < 8; ++i)
                #pragma unroll
                for (int r = 0; r < 4; ++r) acc[i][r] += h[i] * at[r];
        }
        #pragma unroll
        for (int i = 0; i < 8; ++i)
            #pragma unroll
            for (int r = 0; r < 4; ++r)
                if (j0 + r < J_)
                    sm[G2_G + (c0 + i) * AST2 + (j0 + r) * 8 + p] = acc[i][r];
    }
    __syncthreads();

    // ---- store AGG to global in (b, j, ts) column order ----
    {
        int pix0 = blockIdx.x * 8;
        int b = pix0 / 2560, ts0 = pix0 % 2560;
        size_t mb = (size_t)b * 48640 + ts0;
        for (int u = tid; u < 64 * 38; u += 256) {
            int c = u / 38, rr = u % 38;
            int j = rr >> 1, h = (rr & 1) * 4;
            float4 v = *(float4*)&sm[G2_G + c * AST2 + j * 8 + h];
            *(float4*)&g_AG[(size_t)c * NCOLS + mb + (size_t)j * 2560 + h] = v;
        }
    }
}

// ---------------- g3: output GEMM (per-column, coalesced stores) ----------------
__global__ __launch_bounds__(320, 2)
void g3_kernel(const float* __restrict__ Wg, float* __restrict__ out) {
    __shared__ float sw[4096];
    int tid = threadIdx.x;
    for (int q = tid; q < 1024; q += 320)
        *(float4*)&sw[q * 4] = *(const float4*)&Wg[q * 4];
    __syncthreads();

    size_t m = (size_t)blockIdx.x * 320 + tid;
    int b  = (int)(m / 48640);
    int j  = (int)((m / 2560) % J_);
    int ts = (int)(m % 2560);

    u64 acc[32];
    #pragma unroll
    for (int i = 0; i < 32; ++i) acc[i] = 0ull;
    #pragma unroll 8
    for (int c = 0; c < 64; ++c) {
        u64 a2 = dup2(g_AG[(size_t)c * NCOLS + m]);
        #pragma unroll
        for (int q = 0; q < 16; ++q) {
            u64 lo, hi; lds_v2u64(&sw[c * 64 + q * 4], lo, hi);
            fma2(acc[2 * q], lo, a2);
            fma2(acc[2 * q + 1], hi, a2);
        }
    }
    size_t ob = ((size_t)(b * 64) * J_ + j) * 2560 + ts;
    const size_t ostr = (size_t)J_ * 2560;
    #pragma unroll
    for (int i = 0; i < 32; ++i) {
        float lo, hi; upk2(acc[i], lo, hi);
        out[ob + (size_t)(2 * i) * ostr]     = lo;
        out[ob + (size_t)(2 * i + 1) * ostr] = hi;
    }
}

// ------------------------------ launcher --------------------------------------
extern "C" void kernel_launch(void* const* d_in, const int* in_sizes, int n_in,
                              void* d_out, int out_size) {
    const float* x     = (const float*)d_in[0];
    const float* gamma = (const float*)d_in[1];
    const float* beta  = (const float*)d_in[2];
    const float* w1    = (const float*)d_in[3];
    const float* b1    = (const float*)d_in[4];
    const float* w2    = (const float*)d_in[5];
    const float* b2    = (const float*)d_in[6];
    const float* ws1   = (const float*)d_in[7];
    const float* bs1   = (const float*)d_in[8];
    const float* ws2   = (const float*)d_in[9];
    // d_in[10] = bs2 (softmax-invariant), d_in[11] = W
    const float* W     = (const float*)d_in[11];
    float* out = (float*)d_out;

    cudaFuncSetAttribute(g2_kernel,
                         cudaFuncAttributeMaxDynamicSharedMemorySize, G2_BYTES);

    bn_stats_kernel<<<NCH / 8, 256>>>(x, gamma, beta);
    setup_kernel<<<16, 256>>>(w1, w2, ws1, bs1, ws2);
    xn_kernel<<<B_ * 32, 256>>>(x);
    g1_kernel<<<NCOLS / 320, 320>>>(b1, b2);
    g2_kernel<<<NPIX / 8, 256, G2_BYTES>>>();
    g3_kernel<<<NCOLS / 320, 320>>>(W, out);
}

// round 8
// speedup vs baseline: 1.3426x; 1.3426x over previous
#include <cuda_runtime.h>
#include <cuda_bf16.h>
#include <math.h>

// Problem constants
#define B_  16
#define C_  4
#define J_  19
#define T_  256
#define S_  10
#define NCH (C_*J_*T_)          // 19456 BN channels
#define NPIX (B_*T_*S_)         // 40960 pixels
#define EPSV 1e-5f

#define PPB 8                   // pixels per block
#define NCOL 160                // 8 px x 20 cols
#define AST 160                 // activation row stride
#define NTH 320                 // 8 d-groups x 40 col-groups

typedef unsigned long long u64;

// ---- f32x2 packed-math helpers ------------------------------------------------
__device__ __forceinline__ u64 dup2(float a) {
    u64 r; asm("mov.b64 %0, {%1, %1};" : "=l"(r) : "f"(a)); return r;
}
__device__ __forceinline__ void upk2(u64 v, float& lo, float& hi) {
    asm("mov.b64 {%0, %1}, %2;" : "=f"(lo), "=f"(hi) : "l"(v));
}
__device__ __forceinline__ void fma2(u64& d, u64 a, u64 b) {
    asm("fma.rn.f32x2 %0, %1, %2, %0;" : "+l"(d) : "l"(a), "l"(b));
}
__device__ __forceinline__ void lds_v2u64(const float* p, u64& lo, u64& hi) {
    unsigned a = (unsigned)__cvta_generic_to_shared(p);
    asm("ld.shared.v2.u64 {%0, %1}, [%2];" : "=l"(lo), "=l"(hi) : "r"(a));
}

// ---------------- device scratch ----------------------------------------------
__device__ float g_bn_a[NCH];
__device__ float g_bn_b[NCH];
__device__ float g_w1t[C_*64];      // w1t[c][d]
__device__ float g_w2t[64*64];      // w2t[k][d]
__device__ float g_Mt[64*64];       // Mt[b][a]
__device__ float g_v[64];
__device__ float g_xn[(size_t)NPIX * 76];   // normalized input, pixel-major

// ---------------- kernel 1: BN statistics ---------------------------------------
__global__ void bn_stats_kernel(const float* __restrict__ x,
                                const float* __restrict__ gamma,
                                const float* __restrict__ beta) {
    int ch = blockIdx.x * 8 + (threadIdx.x >> 5);
    if (ch >= NCH) return;
    int lane = threadIdx.x & 31;
    float s = 0.f, ss = 0.f;
    for (int e = lane; e < B_ * S_; e += 32) {
        int b = e / S_, si = e % S_;
        float v = x[(b * NCH + ch) * S_ + si];
        s += v; ss += v * v;
    }
    #pragma unroll
    for (int off = 16; off; off >>= 1) {
        s  += __shfl_xor_sync(0xffffffffu, s,  off);
        ss += __shfl_xor_sync(0xffffffffu, ss, off);
    }
    if (lane == 0) {
        const float inv_n = 1.f / (float)(B_ * S_);
        float mean = s * inv_n;
        float var  = ss * inv_n - mean * mean;
        float a = gamma[ch] * rsqrtf(var + EPSV);
        g_bn_a[ch] = a;
        g_bn_b[ch] = beta[ch] - mean * a;
    }
}

// ---------------- kernel 2: precompute M, v, transposed weights -----------------
__global__ void setup_kernel(const float* __restrict__ w1,
                             const float* __restrict__ w2,
                             const float* __restrict__ ws1,
                             const float* __restrict__ bs1,
                             const float* __restrict__ ws2) {
    int idx = blockIdx.x * blockDim.x + threadIdx.x;
    if (idx < 4096) {
        int b = idx >> 6, a = idx & 63;
        float acc = 0.f;
        #pragma unroll 4
        for (int s = 0; s < 128; ++s)
            acc += ws1[s * 64 + a] * ws2[s * 64 + b];
        g_Mt[b * 64 + a] = acc;
        g_w2t[idx] = w2[(idx & 63) * 64 + (idx >> 6)];
    }
    if (idx < C_ * 64) g_w1t[idx] = w1[(idx & 63) * C_ + (idx >> 6)];
    if (idx < 64) {
        float acc = 0.f;
        #pragma unroll 4
        for (int s = 0; s < 128; ++s)
            acc += ws2[s * 64 + idx] * bs1[s];
        g_v[idx] = acc;
    }
}

// ---------------- kernel 3: BN-apply + transpose to pixel-major -----------------
#define XTK 8
__global__ void xn_kernel(const float* __restrict__ x) {
    __shared__ float sa[76 * XTK];
    __shared__ float sb[76 * XTK];
    __shared__ float tile[80 * 80];
    int b  = blockIdx.x >> 5;
    int t0 = (blockIdx.x & 31) * XTK;
    int tid = threadIdx.x;

    for (int u = tid; u < 76 * XTK; u += 256) {
        int ch = u / XTK, tt = u % XTK;
        sa[u] = g_bn_a[ch * 256 + t0 + tt];
        sb[u] = g_bn_b[ch * 256 + t0 + tt];
    }
    __syncthreads();

    for (int u = tid; u < 76 * 20; u += 256) {
        int ch = u / 20, i4 = (u % 20) * 4;
        float4 v = *(const float4*)&x[((size_t)(b * 76 + ch)) * 2560 + t0 * 10 + i4];
        #pragma unroll
        for (int q = 0; q < 4; ++q) {
            int i = i4 + q;
            int tt = i / 10;
            tile[i * 80 + ch] = (&v.x)[q] * sa[ch * XTK + tt] + sb[ch * XTK + tt];
        }
    }
    __syncthreads();

    for (int u = tid; u < 80 * 19; u += 256) {
        int i = u / 19, chq = u % 19;
        float4 v = *(float4*)&tile[i * 80 + chq * 4];
        *(float4*)&g_xn[((size_t)(b * 2560 + t0 * 10 + i)) * 76 + chq * 4] = v;
    }
}

// ---------------- smem layout (float offsets) ----------------------------------
#define OFF_W1T   0        // 256
#define OFF_B1    256      // 64
#define OFF_B2    320      // 64
#define OFF_V     384      // 64
#define OFF_SWB   448      // 4096 time-shared: W2T -> Mt -> W
#define OFF_LT    4544     // 8*380 = 3040, [p][j][k(20)]
#define OFF_VH    7584     // 160
#define OFF_A1    7744     // 64*160 = 10240 : h1 -> G -> AGG
#define OFF_A2    17984    // 64*160 = 10240 : H (front aliased as XN)
#define SMEM_FLOATS 28224
#define SMEM_BYTES (SMEM_FLOATS * 4)   // 112,896 B -> 2 blocks/SM
#define OFF_XN    OFF_A2   // 4*160 = 640, dead once C writes A2

__global__ __launch_bounds__(NTH, 2)
void geo_gcn_main_kernel(const float* __restrict__ b1g,
                         const float* __restrict__ b2g,
                         const float* __restrict__ Wg,
                         float* __restrict__ out) {
    extern __shared__ float sm[];
    const int tid = threadIdx.x;
    const int pix0 = blockIdx.x * PPB;

    // ---- prologue: SWB=W2T, W1T, biases, v, XN ----
    for (int q = tid; q < 1024; q += NTH)
        *(float4*)&sm[OFF_SWB + q * 4] = *(const float4*)&g_w2t[q * 4];
    if (tid < 64) {
        *(float4*)&sm[OFF_W1T + tid * 4] = *(const float4*)&g_w1t[tid * 4];
        sm[OFF_B1 + tid] = b1g[tid];
        sm[OFF_B2 + tid] = b2g[tid];
        sm[OFF_V  + tid] = g_v[tid];
    }
    if (tid < 152) {
        float4 v = *(const float4*)&g_xn[(size_t)pix0 * 76 + tid * 4];
        int g = tid * 4;
        int p = g / 76, off = g % 76;
        #pragma unroll
        for (int u = 0; u < 4; ++u) {
            int ch = off + u;
            int c = ch / 19, j = ch % 19;
            sm[OFF_XN + c * AST + p * 20 + j] = (&v.x)[u];
        }
    } else if (tid < 160) {
        int pp = tid - 152;   // zero j=19 pads
        #pragma unroll
        for (int c = 0; c < C_; ++c)
            sm[OFF_XN + c * AST + pp * 20 + 19] = 0.f;
    }
    __syncthreads();

    const int dg = tid / 40, cg = tid % 40;
    const int d0 = dg * 8, col0 = cg * 4;

    // ================= Phase B: h1 = relu(W1 xn + b1) -> A1 =================
    {
        u64 acc[8][2];
        #pragma unroll
        for (int i = 0; i < 8; ++i) {
            u64 bv = dup2(sm[OFF_B1 + d0 + i]);
            acc[i][0] = bv; acc[i][1] = bv;
        }
        #pragma unroll
        for (int k = 0; k < C_; ++k) {
            float4 w0 = *(const float4*)&sm[OFF_W1T + k * 64 + d0];
            float4 w1 = *(const float4*)&sm[OFF_W1T + k * 64 + d0 + 4];
            u64 a01, a23;
            lds_v2u64(&sm[OFF_XN + k * AST + col0], a01, a23);
            #pragma unroll
            for (int i = 0; i < 8; ++i) {
                u64 wd = dup2(i < 4 ? (&w0.x)[i] : (&w1.x)[i - 4]);
                fma2(acc[i][0], wd, a01);
                fma2(acc[i][1], wd, a23);
            }
        }
        #pragma unroll
        for (int i = 0; i < 8; ++i) {
            float v0, v1, v2, v3;
            upk2(acc[i][0], v0, v1); upk2(acc[i][1], v2, v3);
            *(float4*)&sm[OFF_A1 + (d0 + i) * AST + col0] =
                make_float4(fmaxf(v0,0.f), fmaxf(v1,0.f), fmaxf(v2,0.f), fmaxf(v3,0.f));
        }
    }
    __syncthreads();

    // ================= Phase C: H = relu(W2 h1 + b2) -> A2 =================
    {
        u64 acc[8][2];
        #pragma unroll
        for (int i = 0; i < 8; ++i) {
            u64 bv = dup2(sm[OFF_B2 + d0 + i]);
            acc[i][0] = bv; acc[i][1] = bv;
        }
        #pragma unroll 4
        for (int k = 0; k < 64; ++k) {
            float4 w0 = *(const float4*)&sm[OFF_SWB + k * 64 + d0];
            float4 w1 = *(const float4*)&sm[OFF_SWB + k * 64 + d0 + 4];
            u64 a01, a23;
            lds_v2u64(&sm[OFF_A1 + k * AST + col0], a01, a23);
            #pragma unroll
            for (int i = 0; i < 8; ++i) {
                u64 wd = dup2(i < 4 ? (&w0.x)[i] : (&w1.x)[i - 4]);
                fma2(acc[i][0], wd, a01);
                fma2(acc[i][1], wd, a23);
            }
        }
        #pragma unroll
        for (int i = 0; i < 8; ++i) {
            float v0, v1, v2, v3;
            upk2(acc[i][0], v0, v1); upk2(acc[i][1], v2, v3);
            *(float4*)&sm[OFF_A2 + (d0 + i) * AST + col0] =
                make_float4(fmaxf(v0,0.f), fmaxf(v1,0.f), fmaxf(v2,0.f), fmaxf(v3,0.f));
        }
    }
    __syncthreads();
    // reload SWB = Mt
    for (int q = tid; q < 1024; q += NTH)
        *(float4*)&sm[OFF_SWB + q * 4] = *(const float4*)&g_Mt[q * 4];
    __syncthreads();

    // ================= Phase D: G = M H -> A1 =================
    {
        u64 acc[8][2];
        #pragma unroll
        for (int i = 0; i < 8; ++i) { acc[i][0] = 0ull; acc[i][1] = 0ull; }
        #pragma unroll 4
        for (int k = 0; k < 64; ++k) {
            float4 w0 = *(const float4*)&sm[OFF_SWB + k * 64 + d0];
            float4 w1 = *(const float4*)&sm[OFF_SWB + k * 64 + d0 + 4];
            u64 a01, a23;
            lds_v2u64(&sm[OFF_A2 + k * AST + col0], a01, a23);
            #pragma unroll
            for (int i = 0; i < 8; ++i) {
                u64 wd = dup2(i < 4 ? (&w0.x)[i] : (&w1.x)[i - 4]);
                fma2(acc[i][0], wd, a01);
                fma2(acc[i][1], wd, a23);
            }
        }
        #pragma unroll
        for (int i = 0; i < 8; ++i) {
            float v0, v1, v2, v3;
            upk2(acc[i][0], v0, v1); upk2(acc[i][1], v2, v3);
            *(float4*)&sm[OFF_A1 + (d0 + i) * AST + col0] = make_float4(v0, v1, v2, v3);
        }
    }
    __syncthreads();

    // ===== Phase F: logits LT[p][j][k] = sum_a H[a][j] G[a][k]; vh[p][k] =====
    if (tid < 200) {
        int p  = tid / 25, r = tid % 25;
        int j0 = (r % 5) * 4, k0 = (r / 5) * 4;
        u64 acc2[4][2];
        #pragma unroll
        for (int e = 0; e < 4; ++e) { acc2[e][0] = 0ull; acc2[e][1] = 0ull; }
        #pragma unroll 4
        for (int a = 0; a < 64; ++a) {
            float4 h4 = *(const float4*)&sm[OFF_A2 + a * AST + p * 20 + j0];
            u64 g01, g23;
            lds_v2u64(&sm[OFF_A1 + a * AST + p * 20 + k0], g01, g23);
            #pragma unroll
            for (int e = 0; e < 4; ++e) {
                u64 hd = dup2((&h4.x)[e]);
                fma2(acc2[e][0], hd, g01);
                fma2(acc2[e][1], hd, g23);
            }
        }
        #pragma unroll
        for (int e = 0; e < 4; ++e) {
            if (j0 + e < J_) {
                float l0, l1, l2, l3;
                upk2(acc2[e][0], l0, l1); upk2(acc2[e][1], l2, l3);
                *(float4*)&sm[OFF_LT + p * 380 + (j0 + e) * 20 + k0] =
                    make_float4(l0, l1, l2, l3);
            }
        }
    } else if (tid < 280) {
        for (int u = tid - 200; u < 160; u += 80) {
            int p = u / 20, k = u % 20;
            float a = 0.f;
            #pragma unroll 8
            for (int b = 0; b < 64; ++b)
                a += sm[OFF_V + b] * sm[OFF_A2 + b * AST + p * 20 + k];
            sm[OFF_VH + u] = a;
        }
    }
    __syncthreads();

    // ===== softmax (tid<152) ; SWB=W reload (tid>=152) =====
    if (tid < 152) {
        int p = tid / J_, j = tid % J_;
        int lb = OFF_LT + p * 380 + j * 20;
        float l[J_];
        float mx = -1e30f;
        #pragma unroll
        for (int k = 0; k < J_; ++k) {
            l[k] = sm[lb + k] + sm[OFF_VH + p * 20 + k];
            mx = fmaxf(mx, l[k]);
        }
        float sum = 0.f;
        #pragma unroll
        for (int k = 0; k < J_; ++k) { l[k] = __expf(l[k] - mx); sum += l[k]; }
        float inv = 1.f / sum;
        #pragma unroll
        for (int k = 0; k < J_; ++k) sm[lb + k] = l[k] * inv;
    } else {
        for (int q = tid - 152; q < 1024; q += 168)
            *(float4*)&sm[OFF_SWB + q * 4] = *(const float4*)&Wg[q * 4];
    }
    __syncthreads();

    // ===== AGG[c][j*8+p] = sum_k H[c][p*20+k] att[p][j][k] -> A1 =====
    {
        int c0 = (tid & 7) * 8;
        int rest = tid >> 3;
        int p = rest & 7;
        int j0 = (rest >> 3) * 4;
        float acc[8][4];
        #pragma unroll
        for (int i = 0; i < 8; ++i)
            #pragma unroll
            for (int r = 0; r < 4; ++r) acc[i][r] = 0.f;
        #pragma unroll
        for (int k = 0; k < J_; ++k) {
            float at[4], h[8];
            #pragma unroll
            for (int r = 0; r < 4; ++r)
                at[r] = sm[OFF_LT + p * 380 + (j0 + r) * 20 + k];
            #pragma unroll
            for (int i = 0; i < 8; ++i)
                h[i] = sm[OFF_A2 + (c0 + i) * AST + p * 20 + k];
            #pragma unroll
            for (int i = 0; i < 8; ++i)
                #pragma unroll
                for (int r = 0; r < 4; ++r) acc[i][r] += h[i] * at[r];
        }
        #pragma unroll
        for (int i = 0; i < 8; ++i)
            #pragma unroll
            for (int r = 0; r < 4; ++r)
                if (j0 + r < J_)
                    sm[OFF_A1 + (c0 + i) * AST + (j0 + r) * 8 + p] = acc[i][r];
    }
    __syncthreads();

    // ===== OUT: out[o][j, px] = sum_c W[c][o] AGG[c][col] =====
    {
        u64 acc[8][2];
        #pragma unroll
        for (int i = 0; i < 8; ++i) { acc[i][0] = 0ull; acc[i][1] = 0ull; }
        #pragma unroll 4
        for (int k = 0; k < 64; ++k) {
            float4 w0 = *(const float4*)&sm[OFF_SWB + k * 64 + d0];
            float4 w1 = *(const float4*)&sm[OFF_SWB + k * 64 + d0 + 4];
            u64 a01, a23;
            lds_v2u64(&sm[OFF_A1 + k * AST + col0], a01, a23);
            #pragma unroll
            for (int i = 0; i < 8; ++i) {
                u64 wd = dup2(i < 4 ? (&w0.x)[i] : (&w1.x)[i - 4]);
                fma2(acc[i][0], wd, a01);
                fma2(acc[i][1], wd, a23);
            }
        }
        if (cg < 38) {
            int j  = cg >> 1;
            int pb = (cg & 1) * 4;
            int b    = pix0 / 2560;
            int ts0  = pix0 % 2560;
            #pragma unroll
            for (int i = 0; i < 8; ++i) {
                float v0, v1, v2, v3;
                upk2(acc[i][0], v0, v1); upk2(acc[i][1], v2, v3);
                *(float4*)&out[((size_t)((b * 64 + d0 + i) * J_ + j)) * 2560 + ts0 + pb] =
                    make_float4(v0, v1, v2, v3);
            }
        }
    }
}

// ------------------------------ launcher --------------------------------------
extern "C" void kernel_launch(void* const* d_in, const int* in_sizes, int n_in,
                              void* d_out, int out_size) {
    const float* x     = (const float*)d_in[0];
    const float* gamma = (const float*)d_in[1];
    const float* beta  = (const float*)d_in[2];
    const float* w1    = (const float*)d_in[3];
    const float* b1    = (const float*)d_in[4];
    const float* w2    = (const float*)d_in[5];
    const float* b2    = (const float*)d_in[6];
    const float* ws1   = (const float*)d_in[7];
    const float* bs1   = (const float*)d_in[8];
    const float* ws2   = (const float*)d_in[9];
    // d_in[10] = bs2 (softmax-invariant), d_in[11] = W
    const float* W     = (const float*)d_in[11];
    float* out = (float*)d_out;

    cudaFuncSetAttribute(geo_gcn_main_kernel,
                         cudaFuncAttributeMaxDynamicSharedMemorySize, SMEM_BYTES);

    bn_stats_kernel<<<NCH / 8, 256>>>(x, gamma, beta);
    setup_kernel<<<16, 256>>>(w1, w2, ws1, bs1, ws2);
    xn_kernel<<<B_ * 32, 256>>>(x);
    geo_gcn_main_kernel<<<NPIX / PPB, NTH, SMEM_BYTES>>>(b1, b2, W, out);
}